// round 3
// baseline (speedup 1.0000x reference)
#include <cuda_runtime.h>
#include <cstddef>

// CAN: per-sample 2-layer MLP, B=16384, N=50, D=16, fp32.
// x = relu(x @ W0 + b0); x = relu(x @ W1 + b1)
//
// R3: lane owns 5 rows x 8 cols (20 lanes/sample). W + x staged in shared;
// x lives in registers across both layers; layer-1 halves exchanged via
// shfl_xor(1); packed f32x2 FMA; scattered-but-sector-dense stores.

#define CAN_D 16
#define CAN_N 50
#define R_ROWS 5
#define SPB 16               // samples per block
#define LPS 20               // lanes per sample
#define TPB 320              // SPB * LPS
#define W_FLOATS 544         // 2*(256+16)
#define W_STRIDE 552         // padded floats per sample in smem (16B mult)
#define XBLK 84              // floats per 5-row block in smem (80 data + 4 pad)
#define X_STRIDE 840         // 10 blocks * 84

typedef unsigned long long ull;

#define FMA2(acc, x2, w2) \
    asm("fma.rn.f32x2 %0, %1, %2, %3;" : "=l"(acc) : "l"(x2), "l"(w2), "l"(acc))
#define PACK2(dst, f) \
    asm("mov.b64 %0, {%1, %1};" : "=l"(dst) : "r"(__float_as_uint(f)))
#define UNPACK2(lo, hi, p) \
    asm("mov.b64 {%0, %1}, %2;" : "=r"(lo), "=r"(hi) : "l"(p))

extern __shared__ float smem[];   // [x: SPB*X_STRIDE | w: SPB*W_STRIDE]

// One layer: w = 16B-unit pointer to this sample+layer's slice
// (W rows at idx 4d + ch*2 + {0,1}; bias at 64 + ch*2 + {0,1}).
__device__ __forceinline__ void can_layer(const double2* __restrict__ w, int ch,
                                          const float x[R_ROWS][CAN_D],
                                          ull acc[R_ROWS][4])
{
    double2 ba = w[64 + ch * 2];
    double2 bb = w[64 + ch * 2 + 1];
    ull b0 = __double_as_longlong(ba.x), b1 = __double_as_longlong(ba.y);
    ull b2 = __double_as_longlong(bb.x), b3 = __double_as_longlong(bb.y);
    #pragma unroll
    for (int r = 0; r < R_ROWS; ++r) {
        acc[r][0] = b0; acc[r][1] = b1; acc[r][2] = b2; acc[r][3] = b3;
    }
    #pragma unroll
    for (int d = 0; d < CAN_D; ++d) {
        double2 wa = w[d * 4 + ch * 2];
        double2 wb = w[d * 4 + ch * 2 + 1];
        ull w0 = __double_as_longlong(wa.x), w1 = __double_as_longlong(wa.y);
        ull w2 = __double_as_longlong(wb.x), w3 = __double_as_longlong(wb.y);
        #pragma unroll
        for (int r = 0; r < R_ROWS; ++r) {
            ull px; PACK2(px, x[r][d]);
            FMA2(acc[r][0], px, w0);
            FMA2(acc[r][1], px, w1);
            FMA2(acc[r][2], px, w2);
            FMA2(acc[r][3], px, w3);
        }
    }
}

__global__ __launch_bounds__(TPB, 1)
void can_kernel(const float* __restrict__ user,
                const float* __restrict__ item,
                float* __restrict__ out,
                int B)
{
    const int tid   = threadIdx.x;
    const int sbase = blockIdx.x * SPB;
    const int nsamp = min(SPB, B - sbase);

    float* xs  = smem;
    float* wsm = smem + SPB * X_STRIDE;

    // ---- stage x (into padded 5-row blocks) and W, fully coalesced reads ----
    {
        const float4* __restrict__ gx =
            reinterpret_cast<const float4*>(user + (size_t)sbase * (CAN_N * CAN_D));
        const int nx4 = nsamp * 200;
        for (int i = tid; i < nx4; i += TPB) {
            int s = i / 200, f = i % 200;
            int rb = f / 20, q = f % 20;
            *reinterpret_cast<float4*>(xs + s * X_STRIDE + rb * XBLK + q * 4) = gx[i];
        }
        const float4* __restrict__ gw =
            reinterpret_cast<const float4*>(item + (size_t)sbase * W_FLOATS);
        const int nw4 = nsamp * 136;
        for (int i = tid; i < nw4; i += TPB) {
            int s = i / 136, f = i % 136;
            *reinterpret_cast<float4*>(wsm + s * W_STRIDE + f * 4) = gw[i];
        }
    }
    __syncthreads();

    const int sl = tid / LPS;       // local sample
    const int ls = tid % LPS;
    const int rg = ls >> 1;         // row group: rows rg*5 .. rg*5+4
    const int ch = ls & 1;          // column half: cols ch*8 .. ch*8+7

    // ---- lane's 5 x-rows into registers (20 LDS.128, conflict-staggered) ----
    float x[R_ROWS][CAN_D];
    {
        const double2* __restrict__ x2 =
            reinterpret_cast<const double2*>(xs + sl * X_STRIDE + rg * XBLK);
        #pragma unroll
        for (int r = 0; r < R_ROWS; ++r)
            #pragma unroll
            for (int q = 0; q < 4; ++q) {
                double2 v = x2[r * 4 + q];
                ull lo = __double_as_longlong(v.x), hi = __double_as_longlong(v.y);
                x[r][4 * q]     = __uint_as_float((unsigned)lo);
                x[r][4 * q + 1] = __uint_as_float((unsigned)(lo >> 32));
                x[r][4 * q + 2] = __uint_as_float((unsigned)hi);
                x[r][4 * q + 3] = __uint_as_float((unsigned)(hi >> 32));
            }
    }

    const double2* __restrict__ wbase =
        reinterpret_cast<const double2*>(wsm + sl * W_STRIDE);
    ull acc[R_ROWS][4];

    // ---- layer 0 ----
    can_layer(wbase, ch, x, acc);

    // relu + exchange column halves with partner lane (tid^1: same sample/rows)
    #pragma unroll
    for (int r = 0; r < R_ROWS; ++r)
        #pragma unroll
        for (int j = 0; j < 4; ++j) {
            unsigned lo, hi;
            UNPACK2(lo, hi, acc[r][j]);
            float f0 = fmaxf(__uint_as_float(lo), 0.0f);
            float f1 = fmaxf(__uint_as_float(hi), 0.0f);
            float g0 = __shfl_xor_sync(0xffffffffu, f0, 1);
            float g1 = __shfl_xor_sync(0xffffffffu, f1, 1);
            x[r][ch * 8 + 2 * j]           = f0;
            x[r][ch * 8 + 2 * j + 1]       = f1;
            x[r][(ch ^ 1) * 8 + 2 * j]     = g0;
            x[r][(ch ^ 1) * 8 + 2 * j + 1] = g1;
        }

    // ---- layer 1 (slice at +272 floats = +68 16B-units) ----
    can_layer(wbase + 68, ch, x, acc);

    // ---- relu + store lane's 5x8 tile (2 STG.128 per row) ----
    if (sl < nsamp) {
        float* __restrict__ o = out + (size_t)(sbase + sl) * (CAN_N * CAN_D)
                              + (rg * R_ROWS) * CAN_D + ch * 8;
        #pragma unroll
        for (int r = 0; r < R_ROWS; ++r) {
            unsigned lo0, hi0, lo1, hi1, lo2, hi2, lo3, hi3;
            UNPACK2(lo0, hi0, acc[r][0]);
            UNPACK2(lo1, hi1, acc[r][1]);
            UNPACK2(lo2, hi2, acc[r][2]);
            UNPACK2(lo3, hi3, acc[r][3]);
            float4 v0 = make_float4(fmaxf(__uint_as_float(lo0), 0.0f),
                                    fmaxf(__uint_as_float(hi0), 0.0f),
                                    fmaxf(__uint_as_float(lo1), 0.0f),
                                    fmaxf(__uint_as_float(hi1), 0.0f));
            float4 v1 = make_float4(fmaxf(__uint_as_float(lo2), 0.0f),
                                    fmaxf(__uint_as_float(hi2), 0.0f),
                                    fmaxf(__uint_as_float(lo3), 0.0f),
                                    fmaxf(__uint_as_float(hi3), 0.0f));
            *reinterpret_cast<float4*>(o + r * CAN_D)     = v0;
            *reinterpret_cast<float4*>(o + r * CAN_D + 4) = v1;
        }
    }
}

extern "C" void kernel_launch(void* const* d_in, const int* in_sizes, int n_in,
                              void* d_out, int out_size)
{
    const float* user = (const float*)d_in[0];
    const float* item = (const float*)d_in[1];
    float* out = (float*)d_out;

    const int B = in_sizes[0] / (CAN_N * CAN_D);        // 16384
    const int grid = (B + SPB - 1) / SPB;
    const size_t shbytes = (size_t)(SPB * X_STRIDE + SPB * W_STRIDE) * sizeof(float); // 89088

    cudaFuncSetAttribute(can_kernel, cudaFuncAttributeMaxDynamicSharedMemorySize,
                         (int)shbytes);
    can_kernel<<<grid, TPB, shbytes>>>(user, item, out, B);
}

// round 4
// speedup vs baseline: 1.4640x; 1.4640x over previous
#include <cuda_runtime.h>
#include <cstddef>

// CAN: per-sample 2-layer MLP, B=16384, N=50, D=16, fp32.
// x = relu(x @ W0 + b0); x = relu(x @ W1 + b1)
//
// R4: lane-pair (rg, ch) owns 5 rows; W own-column-half in registers
// (4-d chunks), rows streamed one at a time from smem and overwritten in
// place (pair-private -> __syncwarp only). Coalesced stage-in/copy-out.

#define CAN_D 16
#define CAN_N 50
#define SPB 8                 // samples per block
#define TPB 160               // 8 samples * 20 lanes
#define XBLK 84               // floats per 5-row block (80 data + 4 pad)
#define X_STRIDE 840          // 10 blocks * 84 floats per sample

typedef unsigned long long ull;

#define FMA2(acc, x2, w2) \
    asm("fma.rn.f32x2 %0, %1, %2, %3;" : "=l"(acc) : "l"(x2), "l"(w2), "l"(acc))

__device__ __forceinline__ ull pack2(float a, float b) {
    ull r; asm("mov.b64 %0, {%1, %2};" : "=l"(r) : "f"(a), "f"(b)); return r;
}
__device__ __forceinline__ ull splat2(float a) {
    ull r; asm("mov.b64 %0, {%1, %1};" : "=l"(r) : "f"(a)); return r;
}
__device__ __forceinline__ void unpack2(ull p, float& lo, float& hi) {
    asm("mov.b64 {%0, %1}, %2;" : "=f"(lo), "=f"(hi) : "l"(p));
}

// One layer for the lane's 5 rows. Rows live in smem at xrow (stride 16
// floats); full rows are read, relu(out) own col-half written back in place.
// prm_l: float4 view of this layer's params (W at idx 4d+2ch+j, bias at 64+2ch+j).
__device__ __forceinline__ void can_layer(const float4* __restrict__ prm_l,
                                          float* __restrict__ xrow, int ch)
{
    ull acc[5][4];
    {   // bias init (own 8 cols)
        float4 ba = __ldg(prm_l + 64 + ch * 2);
        float4 bb = __ldg(prm_l + 64 + ch * 2 + 1);
        ull b0 = pack2(ba.x, ba.y), b1 = pack2(ba.z, ba.w);
        ull b2 = pack2(bb.x, bb.y), b3 = pack2(bb.z, bb.w);
        #pragma unroll
        for (int r = 0; r < 5; ++r) {
            acc[r][0] = b0; acc[r][1] = b1; acc[r][2] = b2; acc[r][3] = b3;
        }
    }
    #pragma unroll
    for (int dc = 0; dc < 4; ++dc) {         // 4 d's per chunk
        ull wu[4][4];                        // W[d][own 8 cols], 32 regs
        #pragma unroll
        for (int k = 0; k < 4; ++k) {
            float4 wa = __ldg(prm_l + (4 * dc + k) * 4 + ch * 2);
            float4 wb = __ldg(prm_l + (4 * dc + k) * 4 + ch * 2 + 1);
            wu[k][0] = pack2(wa.x, wa.y); wu[k][1] = pack2(wa.z, wa.w);
            wu[k][2] = pack2(wb.x, wb.y); wu[k][3] = pack2(wb.z, wb.w);
        }
        #pragma unroll
        for (int r = 0; r < 5; ++r) {
            float4 xv = *reinterpret_cast<const float4*>(xrow + r * 16 + dc * 4);
            ull p0 = splat2(xv.x), p1 = splat2(xv.y);
            ull p2 = splat2(xv.z), p3 = splat2(xv.w);
            #pragma unroll
            for (int j = 0; j < 4; ++j) {
                FMA2(acc[r][j], p0, wu[0][j]);
                FMA2(acc[r][j], p1, wu[1][j]);
                FMA2(acc[r][j], p2, wu[2][j]);
                FMA2(acc[r][j], p3, wu[3][j]);
            }
        }
    }
    __syncwarp();   // partner must finish reading these rows before overwrite
    #pragma unroll
    for (int r = 0; r < 5; ++r) {
        float f0, f1, f2, f3, f4, f5, f6, f7;
        unpack2(acc[r][0], f0, f1); unpack2(acc[r][1], f2, f3);
        unpack2(acc[r][2], f4, f5); unpack2(acc[r][3], f6, f7);
        float4 v0 = make_float4(fmaxf(f0, 0.f), fmaxf(f1, 0.f),
                                fmaxf(f2, 0.f), fmaxf(f3, 0.f));
        float4 v1 = make_float4(fmaxf(f4, 0.f), fmaxf(f5, 0.f),
                                fmaxf(f6, 0.f), fmaxf(f7, 0.f));
        *reinterpret_cast<float4*>(xrow + r * 16 + ch * 8)     = v0;
        *reinterpret_cast<float4*>(xrow + r * 16 + ch * 8 + 4) = v1;
    }
    __syncwarp();   // writes visible to partner before next layer reads
}

__global__ __launch_bounds__(TPB, 4)
void can_kernel(const float* __restrict__ user,
                const float* __restrict__ item,
                float* __restrict__ out,
                int B)
{
    __shared__ __align__(16) float xs[SPB * X_STRIDE];   // 26.9 KB

    const int tid   = threadIdx.x;
    const int sbase = blockIdx.x * SPB;
    const int nsamp = min(SPB, B - sbase);
    const int nf4   = nsamp * 200;

    // ---- stage x in, warp-coalesced float4, into padded 5-row blocks ----
    {
        const float4* __restrict__ gx =
            reinterpret_cast<const float4*>(user + (size_t)sbase * (CAN_N * CAN_D));
        #pragma unroll
        for (int k = 0; k < 10; ++k) {
            int i = tid + k * TPB;
            if (i < nf4) {
                int s = i / 200, f = i - s * 200;
                int rb = f / 20, q = f - rb * 20;
                *reinterpret_cast<float4*>(xs + s * X_STRIDE + rb * XBLK + q * 4) = gx[i];
            }
        }
    }
    __syncthreads();

    const int sl = tid / 20;
    const int ls = tid - sl * 20;
    const int rg = ls >> 1;
    const int ch = ls & 1;

    if (sl < nsamp) {
        const float4* __restrict__ prm =
            reinterpret_cast<const float4*>(item + (size_t)(sbase + sl) * 544);
        float* xrow = xs + sl * X_STRIDE + rg * XBLK;
        can_layer(prm,      xrow, ch);    // layer 0
        can_layer(prm + 68, xrow, ch);    // layer 1 (params at +272 floats)
    }
    __syncthreads();

    // ---- copy result out, warp-coalesced float4 ----
    {
        float4* __restrict__ go =
            reinterpret_cast<float4*>(out + (size_t)sbase * (CAN_N * CAN_D));
        #pragma unroll
        for (int k = 0; k < 10; ++k) {
            int i = tid + k * TPB;
            if (i < nf4) {
                int s = i / 200, f = i - s * 200;
                int rb = f / 20, q = f - rb * 20;
                go[i] = *reinterpret_cast<const float4*>(xs + s * X_STRIDE + rb * XBLK + q * 4);
            }
        }
    }
}

extern "C" void kernel_launch(void* const* d_in, const int* in_sizes, int n_in,
                              void* d_out, int out_size)
{
    const float* user = (const float*)d_in[0];
    const float* item = (const float*)d_in[1];
    float* out = (float*)d_out;

    const int B = in_sizes[0] / (CAN_N * CAN_D);   // 16384
    const int grid = (B + SPB - 1) / SPB;

    can_kernel<<<grid, TPB>>>(user, item, out, B);
}

// round 5
// speedup vs baseline: 1.7055x; 1.1649x over previous
#include <cuda_runtime.h>
#include <cstddef>

// CAN: per-sample 2-layer MLP, B=16384, N=50, D=16, fp32.
// x = relu(x @ W0 + b0); x = relu(x @ W1 + b1)
//
// R5: lane-pair (rg, ch) owns 5 rows x 8 cols. W AND x staged in shared
// (coalesced); per-lane W read via LDS in 2-d register chunks; rows
// overwritten in place (pair-private -> __syncwarp). 5 blocks/SM target.

#define CAN_D 16
#define CAN_N 50
#define SPB 8                 // samples per block
#define TPB 160               // 8 samples * 20 lanes
#define XBLK 84               // floats per 5-row block (80 data + 4 pad)
#define X_STRIDE 840          // 10 blocks * 84 floats per sample
#define W_FLOATS 544
#define W_STRIDE 556          // padded: 556 mod 32 = 12 -> bank-disjoint samples

typedef unsigned long long ull;

#define FMA2(acc, x2, w2) \
    asm("fma.rn.f32x2 %0, %1, %2, %3;" : "=l"(acc) : "l"(x2), "l"(w2), "l"(acc))

__device__ __forceinline__ ull pack2(float a, float b) {
    ull r; asm("mov.b64 %0, {%1, %2};" : "=l"(r) : "f"(a), "f"(b)); return r;
}
__device__ __forceinline__ ull splat2(float a) {
    ull r; asm("mov.b64 %0, {%1, %1};" : "=l"(r) : "f"(a)); return r;
}
__device__ __forceinline__ void unpack2(ull p, float& lo, float& hi) {
    asm("mov.b64 {%0, %1}, %2;" : "=f"(lo), "=f"(hi) : "l"(p));
}

// One layer for the lane's 5 rows. wl = float4 view (smem) of this layer's
// params: W row d at idx 4d + 2ch + j, bias at 64 + 2ch + j.
__device__ __forceinline__ void can_layer(const float4* __restrict__ wl,
                                          float* __restrict__ xrow, int ch)
{
    ull acc[5][4];
    {
        float4 ba = wl[64 + ch * 2];
        float4 bb = wl[64 + ch * 2 + 1];
        ull b0 = pack2(ba.x, ba.y), b1 = pack2(ba.z, ba.w);
        ull b2 = pack2(bb.x, bb.y), b3 = pack2(bb.z, bb.w);
        #pragma unroll
        for (int r = 0; r < 5; ++r) {
            acc[r][0] = b0; acc[r][1] = b1; acc[r][2] = b2; acc[r][3] = b3;
        }
    }
    #pragma unroll
    for (int dc = 0; dc < 8; ++dc) {          // 2 d's per chunk
        ull wu[2][4];                         // 16 regs
        #pragma unroll
        for (int k = 0; k < 2; ++k) {
            float4 wa = wl[(2 * dc + k) * 4 + ch * 2];
            float4 wb = wl[(2 * dc + k) * 4 + ch * 2 + 1];
            wu[k][0] = pack2(wa.x, wa.y); wu[k][1] = pack2(wa.z, wa.w);
            wu[k][2] = pack2(wb.x, wb.y); wu[k][3] = pack2(wb.z, wb.w);
        }
        #pragma unroll
        for (int r = 0; r < 5; ++r) {
            float2 xv = *reinterpret_cast<const float2*>(xrow + r * 16 + 2 * dc);
            ull p0 = splat2(xv.x), p1 = splat2(xv.y);
            #pragma unroll
            for (int j = 0; j < 4; ++j) {
                FMA2(acc[r][j], p0, wu[0][j]);
                FMA2(acc[r][j], p1, wu[1][j]);
            }
        }
    }
    __syncwarp();   // partner must finish reading rows before overwrite
    #pragma unroll
    for (int r = 0; r < 5; ++r) {
        float f0, f1, f2, f3, f4, f5, f6, f7;
        unpack2(acc[r][0], f0, f1); unpack2(acc[r][1], f2, f3);
        unpack2(acc[r][2], f4, f5); unpack2(acc[r][3], f6, f7);
        float4 v0 = make_float4(fmaxf(f0, 0.f), fmaxf(f1, 0.f),
                                fmaxf(f2, 0.f), fmaxf(f3, 0.f));
        float4 v1 = make_float4(fmaxf(f4, 0.f), fmaxf(f5, 0.f),
                                fmaxf(f6, 0.f), fmaxf(f7, 0.f));
        *reinterpret_cast<float4*>(xrow + r * 16 + ch * 8)     = v0;
        *reinterpret_cast<float4*>(xrow + r * 16 + ch * 8 + 4) = v1;
    }
    __syncwarp();   // writes visible to partner before next layer
}

__global__ __launch_bounds__(TPB, 5)
void can_kernel(const float* __restrict__ user,
                const float* __restrict__ item,
                float* __restrict__ out,
                int B)
{
    __shared__ __align__(16) float xs[SPB * X_STRIDE];   // 26.9 KB
    __shared__ __align__(16) float ws[SPB * W_STRIDE];   // 17.8 KB

    const int tid   = threadIdx.x;
    const int sbase = blockIdx.x * SPB;
    const int nsamp = min(SPB, B - sbase);
    const int nf4   = nsamp * 200;
    const int nw4   = nsamp * 136;

    // ---- stage x and W, warp-coalesced float4 ----
    {
        const float4* __restrict__ gx =
            reinterpret_cast<const float4*>(user + (size_t)sbase * (CAN_N * CAN_D));
        #pragma unroll
        for (int k = 0; k < 10; ++k) {
            int i = tid + k * TPB;
            if (i < nf4) {
                int s = i / 200, f = i - s * 200;
                int rb = f / 20, q = f - rb * 20;
                *reinterpret_cast<float4*>(xs + s * X_STRIDE + rb * XBLK + q * 4) = gx[i];
            }
        }
        const float4* __restrict__ gw =
            reinterpret_cast<const float4*>(item + (size_t)sbase * W_FLOATS);
        #pragma unroll
        for (int k = 0; k < 7; ++k) {
            int i = tid + k * TPB;
            if (i < nw4) {
                int s = i / 136, f = i - s * 136;
                *reinterpret_cast<float4*>(ws + s * W_STRIDE + f * 4) = gw[i];
            }
        }
    }
    __syncthreads();

    const int sl = tid / 20;
    const int ls = tid - sl * 20;
    const int rg = ls >> 1;
    const int ch = ls & 1;

    if (sl < nsamp) {
        const float4* __restrict__ wl =
            reinterpret_cast<const float4*>(ws + sl * W_STRIDE);
        float* xrow = xs + sl * X_STRIDE + rg * XBLK;
        can_layer(wl,      xrow, ch);     // layer 0
        can_layer(wl + 68, xrow, ch);     // layer 1 (+272 floats)
    }
    __syncthreads();

    // ---- copy result out, warp-coalesced float4 ----
    {
        float4* __restrict__ go =
            reinterpret_cast<float4*>(out + (size_t)sbase * (CAN_N * CAN_D));
        #pragma unroll
        for (int k = 0; k < 10; ++k) {
            int i = tid + k * TPB;
            if (i < nf4) {
                int s = i / 200, f = i - s * 200;
                int rb = f / 20, q = f - rb * 20;
                go[i] = *reinterpret_cast<const float4*>(xs + s * X_STRIDE + rb * XBLK + q * 4);
            }
        }
    }
}

extern "C" void kernel_launch(void* const* d_in, const int* in_sizes, int n_in,
                              void* d_out, int out_size)
{
    const float* user = (const float*)d_in[0];
    const float* item = (const float*)d_in[1];
    float* out = (float*)d_out;

    const int B = in_sizes[0] / (CAN_N * CAN_D);   // 16384
    const int grid = (B + SPB - 1) / SPB;

    can_kernel<<<grid, TPB>>>(user, item, out, B);
}

// round 6
// speedup vs baseline: 1.9651x; 1.1522x over previous
#include <cuda_runtime.h>
#include <cstddef>

// CAN: per-sample 2-layer MLP, B=16384, N=50, D=16, fp32.
// x = relu(x @ W0 + b0); x = relu(x @ W1 + b1)
//
// R6: 40 lanes/sample: quad (rg, ch) -> lane owns 5 rows x 4 cols.
// acc = 10 ull regs, W window 8 regs -> <=51 regs, 4 blocks/SM, 40 warps.
// x + W staged in shared; layer0 in-place (quad-private, __syncwarp);
// layer1 stores straight from accumulators to global.

#define CAN_D 16
#define CAN_N 50
#define SPB 8                 // samples per block
#define TPB 320               // 8 samples * 40 lanes
#define XBLK 84               // floats per 5-row block (80 data + 4 pad)
#define X_STRIDE 840          // 10 blocks * 84 floats per sample
#define W_FLOATS 544
#define W_STRIDE 556          // padded floats per sample

typedef unsigned long long ull;

#define FMA2(acc, x2, w2) \
    asm("fma.rn.f32x2 %0, %1, %2, %3;" : "=l"(acc) : "l"(x2), "l"(w2), "l"(acc))

__device__ __forceinline__ ull pack2(float a, float b) {
    ull r; asm("mov.b64 %0, {%1, %2};" : "=l"(r) : "f"(a), "f"(b)); return r;
}
__device__ __forceinline__ ull splat2(float a) {
    ull r; asm("mov.b64 %0, {%1, %1};" : "=l"(r) : "f"(a)); return r;
}
__device__ __forceinline__ void unpack2(ull p, float& lo, float& hi) {
    asm("mov.b64 {%0, %1}, %2;" : "=f"(lo), "=f"(hi) : "l"(p));
}

// Accumulate one layer for lane's 5 rows x 4 cols.
// wl: float4 view of this layer's params (W row d quarter ch at idx 4d+ch,
// bias quarter at 64+ch). xrow: lane's 5 rows in smem (stride 16 floats).
__device__ __forceinline__ void can_core(const float4* __restrict__ wl,
                                         const float* __restrict__ xrow,
                                         int ch, ull acc[5][2])
{
    {
        float4 b = wl[64 + ch];
        ull b0 = pack2(b.x, b.y), b1 = pack2(b.z, b.w);
        #pragma unroll
        for (int r = 0; r < 5; ++r) { acc[r][0] = b0; acc[r][1] = b1; }
    }
    #pragma unroll
    for (int dc = 0; dc < 8; ++dc) {              // 2 d's per chunk
        float4 wa = wl[(2 * dc) * 4 + ch];        // W row 2dc,   own 4 cols
        float4 wb = wl[(2 * dc + 1) * 4 + ch];    // W row 2dc+1, own 4 cols
        ull w00 = pack2(wa.x, wa.y), w01 = pack2(wa.z, wa.w);
        ull w10 = pack2(wb.x, wb.y), w11 = pack2(wb.z, wb.w);
        #pragma unroll
        for (int r = 0; r < 5; ++r) {
            float2 xv = *reinterpret_cast<const float2*>(xrow + r * 16 + 2 * dc);
            ull p0 = splat2(xv.x), p1 = splat2(xv.y);
            FMA2(acc[r][0], p0, w00);
            FMA2(acc[r][1], p0, w01);
            FMA2(acc[r][0], p1, w10);
            FMA2(acc[r][1], p1, w11);
        }
    }
}

__global__ __launch_bounds__(TPB, 4)
void can_kernel(const float* __restrict__ user,
                const float* __restrict__ item,
                float* __restrict__ out,
                int B)
{
    __shared__ __align__(16) float xs[SPB * X_STRIDE];   // 26.9 KB
    __shared__ __align__(16) float ws[SPB * W_STRIDE];   // 17.8 KB

    const int tid   = threadIdx.x;
    const int sbase = blockIdx.x * SPB;
    const int nsamp = min(SPB, B - sbase);
    const int nf4   = nsamp * 200;
    const int nw4   = nsamp * 136;

    // ---- stage x and W, warp-coalesced float4 ----
    {
        const float4* __restrict__ gx =
            reinterpret_cast<const float4*>(user + (size_t)sbase * (CAN_N * CAN_D));
        #pragma unroll
        for (int k = 0; k < 5; ++k) {
            int i = tid + k * TPB;
            if (i < nf4) {
                int s = i / 200, f = i - s * 200;
                int rb = f / 20, q = f - rb * 20;
                *reinterpret_cast<float4*>(xs + s * X_STRIDE + rb * XBLK + q * 4) = gx[i];
            }
        }
        const float4* __restrict__ gw =
            reinterpret_cast<const float4*>(item + (size_t)sbase * W_FLOATS);
        #pragma unroll
        for (int k = 0; k < 4; ++k) {
            int i = tid + k * TPB;
            if (i < nw4) {
                int s = i / 136, f = i - s * 136;
                *reinterpret_cast<float4*>(ws + s * W_STRIDE + f * 4) = gw[i];
            }
        }
    }
    __syncthreads();

    const int sl = tid / 40;        // local sample
    const int ls = tid - sl * 40;
    const int rg = ls >> 2;         // row group: rows rg*5 .. rg*5+4
    const int ch = ls & 3;          // column quarter: cols ch*4 .. ch*4+3

    if (sl < nsamp) {
        const float4* __restrict__ wl =
            reinterpret_cast<const float4*>(ws + sl * W_STRIDE);
        float* __restrict__ xrow = xs + sl * X_STRIDE + rg * XBLK;
        ull acc[5][2];

        // ---- layer 0: accumulate, relu, write own quarter back in place ----
        can_core(wl, xrow, ch, acc);
        __syncwarp();               // quad must finish reading before overwrite
        #pragma unroll
        for (int r = 0; r < 5; ++r) {
            float f0, f1, f2, f3;
            unpack2(acc[r][0], f0, f1);
            unpack2(acc[r][1], f2, f3);
            *reinterpret_cast<float4*>(xrow + r * 16 + ch * 4) =
                make_float4(fmaxf(f0, 0.f), fmaxf(f1, 0.f),
                            fmaxf(f2, 0.f), fmaxf(f3, 0.f));
        }
        __syncwarp();               // quad writes visible before layer-1 reads

        // ---- layer 1: accumulate, relu, store straight to global ----
        can_core(wl + 68, xrow, ch, acc);   // layer-1 params at +272 floats
        float* __restrict__ gout = out + (size_t)(sbase + sl) * (CAN_N * CAN_D)
                                 + (rg * 5) * CAN_D + ch * 4;
        #pragma unroll
        for (int r = 0; r < 5; ++r) {
            float f0, f1, f2, f3;
            unpack2(acc[r][0], f0, f1);
            unpack2(acc[r][1], f2, f3);
            *reinterpret_cast<float4*>(gout + r * CAN_D) =
                make_float4(fmaxf(f0, 0.f), fmaxf(f1, 0.f),
                            fmaxf(f2, 0.f), fmaxf(f3, 0.f));
        }
    }
}

extern "C" void kernel_launch(void* const* d_in, const int* in_sizes, int n_in,
                              void* d_out, int out_size)
{
    const float* user = (const float*)d_in[0];
    const float* item = (const float*)d_in[1];
    float* out = (float*)d_out;

    const int B = in_sizes[0] / (CAN_N * CAN_D);   // 16384
    const int grid = (B + SPB - 1) / SPB;

    can_kernel<<<grid, TPB>>>(user, item, out, B);
}

// round 7
// speedup vs baseline: 2.0315x; 1.0338x over previous
#include <cuda_runtime.h>
#include <cstddef>

// CAN: per-sample 2-layer MLP, B=16384, N=50, D=16, fp32.
// x = relu(x @ W0 + b0); x = relu(x @ W1 + b1)
//
// R7: quad (rg, ch) -> lane owns 5 rows x 4 cols. 4-d chunks: x via LDS.128
// (20/layer), W window 16 regs, W_STRIDE=560 for conflict-free straddled
// warps. SPB=7/TPB=280 to hold 4 blocks/SM at ~56 regs. Layer-1 stores
// straight from accumulators.

#define CAN_D 16
#define CAN_N 50
#define SPB 7                 // samples per block
#define TPB 280               // 7 samples * 40 lanes
#define XBLK 84               // floats per 5-row block (80 data + 4 pad)
#define X_STRIDE 840          // 10 blocks * 84 floats per sample
#define W_FLOATS 544
#define W_STRIDE 560          // mod 32 banks = 16 -> straddle-conflict-free

typedef unsigned long long ull;

#define FMA2(acc, x2, w2) \
    asm("fma.rn.f32x2 %0, %1, %2, %3;" : "=l"(acc) : "l"(x2), "l"(w2), "l"(acc))

__device__ __forceinline__ ull pack2(float a, float b) {
    ull r; asm("mov.b64 %0, {%1, %2};" : "=l"(r) : "f"(a), "f"(b)); return r;
}
__device__ __forceinline__ ull splat2(float a) {
    ull r; asm("mov.b64 %0, {%1, %1};" : "=l"(r) : "f"(a)); return r;
}
__device__ __forceinline__ void unpack2(ull p, float& lo, float& hi) {
    asm("mov.b64 {%0, %1}, %2;" : "=f"(lo), "=f"(hi) : "l"(p));
}

// One layer for lane's 5 rows x 4 cols. wl: float4 view of layer params
// (W row d quarter ch at idx 4d+ch, bias quarter at 64+ch). xrow: lane's
// 5 rows in smem, stride 16 floats.
__device__ __forceinline__ void can_core(const float4* __restrict__ wl,
                                         const float* __restrict__ xrow,
                                         int ch, ull acc[5][2])
{
    {
        float4 b = wl[64 + ch];
        ull b0 = pack2(b.x, b.y), b1 = pack2(b.z, b.w);
        #pragma unroll
        for (int r = 0; r < 5; ++r) { acc[r][0] = b0; acc[r][1] = b1; }
    }
    #pragma unroll
    for (int dc = 0; dc < 4; ++dc) {              // 4 d's per chunk
        ull wu[4][2];                             // 16 regs
        #pragma unroll
        for (int k = 0; k < 4; ++k) {
            float4 w = wl[(4 * dc + k) * 4 + ch];
            wu[k][0] = pack2(w.x, w.y);
            wu[k][1] = pack2(w.z, w.w);
        }
        #pragma unroll
        for (int r = 0; r < 5; ++r) {
            float4 xv = *reinterpret_cast<const float4*>(xrow + r * 16 + 4 * dc);
            ull p0 = splat2(xv.x), p1 = splat2(xv.y);
            ull p2 = splat2(xv.z), p3 = splat2(xv.w);
            FMA2(acc[r][0], p0, wu[0][0]);  FMA2(acc[r][1], p0, wu[0][1]);
            FMA2(acc[r][0], p1, wu[1][0]);  FMA2(acc[r][1], p1, wu[1][1]);
            FMA2(acc[r][0], p2, wu[2][0]);  FMA2(acc[r][1], p2, wu[2][1]);
            FMA2(acc[r][0], p3, wu[3][0]);  FMA2(acc[r][1], p3, wu[3][1]);
        }
    }
}

__global__ __launch_bounds__(TPB, 4)
void can_kernel(const float* __restrict__ user,
                const float* __restrict__ item,
                float* __restrict__ out,
                int B)
{
    __shared__ __align__(16) float xs[SPB * X_STRIDE];   // 23.5 KB
    __shared__ __align__(16) float ws[SPB * W_STRIDE];   // 15.7 KB

    const int tid   = threadIdx.x;
    const int sbase = blockIdx.x * SPB;
    const int nsamp = min(SPB, B - sbase);
    const int nf4   = nsamp * 200;                        // <= 1400
    const int nw4   = nsamp * 136;                        // <= 952

    // ---- stage x and W, warp-coalesced float4 ----
    {
        const float4* __restrict__ gx =
            reinterpret_cast<const float4*>(user + (size_t)sbase * (CAN_N * CAN_D));
        #pragma unroll
        for (int k = 0; k < 5; ++k) {
            int i = tid + k * TPB;
            if (i < nf4) {
                int s = i / 200, f = i - s * 200;
                int rb = f / 20, q = f - rb * 20;
                *reinterpret_cast<float4*>(xs + s * X_STRIDE + rb * XBLK + q * 4) = gx[i];
            }
        }
        const float4* __restrict__ gw =
            reinterpret_cast<const float4*>(item + (size_t)sbase * W_FLOATS);
        #pragma unroll
        for (int k = 0; k < 4; ++k) {
            int i = tid + k * TPB;
            if (i < nw4) {
                int s = i / 136, f = i - s * 136;
                *reinterpret_cast<float4*>(ws + s * W_STRIDE + f * 4) = gw[i];
            }
        }
    }
    __syncthreads();

    const int sl = tid / 40;        // local sample
    const int ls = tid - sl * 40;
    const int rg = ls >> 2;         // row group: rows rg*5 .. rg*5+4
    const int ch = ls & 3;          // column quarter: cols ch*4 .. ch*4+3

    if (sl < nsamp) {
        const float4* __restrict__ wl =
            reinterpret_cast<const float4*>(ws + sl * W_STRIDE);
        float* __restrict__ xrow = xs + sl * X_STRIDE + rg * XBLK;
        ull acc[5][2];

        // ---- layer 0: accumulate, relu, write own quarter back in place ----
        can_core(wl, xrow, ch, acc);
        __syncwarp();               // quad finishes reading before overwrite
        #pragma unroll
        for (int r = 0; r < 5; ++r) {
            float f0, f1, f2, f3;
            unpack2(acc[r][0], f0, f1);
            unpack2(acc[r][1], f2, f3);
            *reinterpret_cast<float4*>(xrow + r * 16 + ch * 4) =
                make_float4(fmaxf(f0, 0.f), fmaxf(f1, 0.f),
                            fmaxf(f2, 0.f), fmaxf(f3, 0.f));
        }
        __syncwarp();               // quad writes visible before layer-1 reads

        // ---- layer 1: accumulate, relu, store straight to global ----
        can_core(wl + 68, xrow, ch, acc);   // layer-1 params at +272 floats
        float* __restrict__ gout = out + (size_t)(sbase + sl) * (CAN_N * CAN_D)
                                 + (rg * 5) * CAN_D + ch * 4;
        #pragma unroll
        for (int r = 0; r < 5; ++r) {
            float f0, f1, f2, f3;
            unpack2(acc[r][0], f0, f1);
            unpack2(acc[r][1], f2, f3);
            *reinterpret_cast<float4*>(gout + r * CAN_D) =
                make_float4(fmaxf(f0, 0.f), fmaxf(f1, 0.f),
                            fmaxf(f2, 0.f), fmaxf(f3, 0.f));
        }
    }
}

extern "C" void kernel_launch(void* const* d_in, const int* in_sizes, int n_in,
                              void* d_out, int out_size)
{
    const float* user = (const float*)d_in[0];
    const float* item = (const float*)d_in[1];
    float* out = (float*)d_out;

    const int B = in_sizes[0] / (CAN_N * CAN_D);   // 16384
    const int grid = (B + SPB - 1) / SPB;

    can_kernel<<<grid, TPB>>>(user, item, out, B);
}

// round 8
// speedup vs baseline: 2.4578x; 1.2098x over previous
#include <cuda_runtime.h>
#include <cstddef>

// CAN: per-sample 2-layer MLP, B=16384, N=50, D=16, fp32.
// x = relu(x @ W0 + b0); x = relu(x @ W1 + b1)
//
// R8: quad (rg, ch) -> lane owns 10 rows x 4 cols (20 lanes/sample).
// cp.async staging for x and W; W window 16 regs (4-d chunks); layer-0
// overwrites x in place (quad-private, __syncwarp); layer-1 stores straight
// from accumulators. 5 blocks/SM target, LSU-instruction-minimized.

#define CAN_D 16
#define CAN_N 50
#define SPB 8                 // samples per block
#define TPB 160               // 8 samples * 20 lanes
#define XBLK 164              // floats per 10-row block (160 data + 4 pad)
#define X_STRIDE 820          // 5 blocks * 164 floats per sample
#define W_FLOATS 544
#define W_STRIDE 560          // mod 32 banks = 16 -> straddle-conflict-free

typedef unsigned long long ull;

#define FMA2(acc, x2, w2) \
    asm("fma.rn.f32x2 %0, %1, %2, %3;" : "=l"(acc) : "l"(x2), "l"(w2), "l"(acc))

__device__ __forceinline__ ull pack2(float a, float b) {
    ull r; asm("mov.b64 %0, {%1, %2};" : "=l"(r) : "f"(a), "f"(b)); return r;
}
__device__ __forceinline__ ull splat2(float a) {
    ull r; asm("mov.b64 %0, {%1, %1};" : "=l"(r) : "f"(a)); return r;
}
__device__ __forceinline__ void unpack2(ull p, float& lo, float& hi) {
    asm("mov.b64 {%0, %1}, %2;" : "=f"(lo), "=f"(hi) : "l"(p));
}
__device__ __forceinline__ void cp_async16(unsigned dst, const void* src) {
    asm volatile("cp.async.cg.shared.global [%0], [%1], 16;"
                 :: "r"(dst), "l"(src));
}

// One layer for lane's 10 rows x 4 cols. wl: float4 view of layer params
// (W row d quarter ch at idx 4d+ch, bias quarter at 64+ch). xrow: lane's
// 10 rows in smem, stride 16 floats.
__device__ __forceinline__ void can_core(const float4* __restrict__ wl,
                                         const float* __restrict__ xrow,
                                         int ch, ull acc[10][2])
{
    {
        float4 b = wl[64 + ch];
        ull b0 = pack2(b.x, b.y), b1 = pack2(b.z, b.w);
        #pragma unroll
        for (int r = 0; r < 10; ++r) { acc[r][0] = b0; acc[r][1] = b1; }
    }
    #pragma unroll
    for (int dc = 0; dc < 4; ++dc) {              // 4 d's per chunk
        ull wu[4][2];                             // 16 regs
        #pragma unroll
        for (int k = 0; k < 4; ++k) {
            float4 w = wl[(4 * dc + k) * 4 + ch];
            wu[k][0] = pack2(w.x, w.y);
            wu[k][1] = pack2(w.z, w.w);
        }
        #pragma unroll
        for (int r = 0; r < 10; ++r) {
            float4 xv = *reinterpret_cast<const float4*>(xrow + r * 16 + 4 * dc);
            ull p0 = splat2(xv.x), p1 = splat2(xv.y);
            ull p2 = splat2(xv.z), p3 = splat2(xv.w);
            FMA2(acc[r][0], p0, wu[0][0]);  FMA2(acc[r][1], p0, wu[0][1]);
            FMA2(acc[r][0], p1, wu[1][0]);  FMA2(acc[r][1], p1, wu[1][1]);
            FMA2(acc[r][0], p2, wu[2][0]);  FMA2(acc[r][1], p2, wu[2][1]);
            FMA2(acc[r][0], p3, wu[3][0]);  FMA2(acc[r][1], p3, wu[3][1]);
        }
    }
}

__global__ __launch_bounds__(TPB, 5)
void can_kernel(const float* __restrict__ user,
                const float* __restrict__ item,
                float* __restrict__ out,
                int B)
{
    __shared__ __align__(16) float xs[SPB * X_STRIDE];   // 26.2 KB
    __shared__ __align__(16) float ws[SPB * W_STRIDE];   // 17.9 KB

    const int tid   = threadIdx.x;
    const int sbase = blockIdx.x * SPB;
    const int nsamp = min(SPB, B - sbase);
    const int nf4   = nsamp * 200;                        // <= 1600
    const int nw4   = nsamp * 136;                        // <= 1088

    // ---- stage x and W via cp.async (no register round-trip) ----
    {
        const float4* __restrict__ gx =
            reinterpret_cast<const float4*>(user + (size_t)sbase * (CAN_N * CAN_D));
        #pragma unroll
        for (int k = 0; k < 10; ++k) {
            int i = tid + k * TPB;
            if (i < nf4) {
                int s = i / 200, f = i - s * 200;
                int row = f >> 2, q = f & 3;
                int rb = row / 10, rr = row - rb * 10;
                unsigned dst = (unsigned)__cvta_generic_to_shared(
                    xs + s * X_STRIDE + rb * XBLK + rr * 16 + q * 4);
                cp_async16(dst, gx + i);
            }
        }
        const float4* __restrict__ gw =
            reinterpret_cast<const float4*>(item + (size_t)sbase * W_FLOATS);
        #pragma unroll
        for (int k = 0; k < 7; ++k) {
            int i = tid + k * TPB;
            if (i < nw4) {
                int s = i / 136, f = i - s * 136;
                unsigned dst = (unsigned)__cvta_generic_to_shared(
                    ws + s * W_STRIDE + f * 4);
                cp_async16(dst, gw + i);
            }
        }
        asm volatile("cp.async.commit_group;" ::: "memory");
        asm volatile("cp.async.wait_group 0;"  ::: "memory");
    }
    __syncthreads();

    const int sl = tid / 20;        // local sample
    const int ls = tid - sl * 20;
    const int rg = ls >> 2;         // row group: rows rg*10 .. rg*10+9
    const int ch = ls & 3;          // column quarter: cols ch*4 .. ch*4+3

    if (sl < nsamp) {
        const float4* __restrict__ wl =
            reinterpret_cast<const float4*>(ws + sl * W_STRIDE);
        float* __restrict__ xrow = xs + sl * X_STRIDE + rg * XBLK;
        ull acc[10][2];

        // ---- layer 0: accumulate, relu, write own quarter back in place ----
        can_core(wl, xrow, ch, acc);
        __syncwarp();               // quad finishes reading before overwrite
        #pragma unroll
        for (int r = 0; r < 10; ++r) {
            float f0, f1, f2, f3;
            unpack2(acc[r][0], f0, f1);
            unpack2(acc[r][1], f2, f3);
            *reinterpret_cast<float4*>(xrow + r * 16 + ch * 4) =
                make_float4(fmaxf(f0, 0.f), fmaxf(f1, 0.f),
                            fmaxf(f2, 0.f), fmaxf(f3, 0.f));
        }
        __syncwarp();               // quad writes visible before layer-1 reads

        // ---- layer 1: accumulate, relu, store straight to global ----
        can_core(wl + 68, xrow, ch, acc);   // layer-1 params at +272 floats
        float* __restrict__ gout = out + (size_t)(sbase + sl) * (CAN_N * CAN_D)
                                 + (rg * 10) * CAN_D + ch * 4;
        #pragma unroll
        for (int r = 0; r < 10; ++r) {
            float f0, f1, f2, f3;
            unpack2(acc[r][0], f0, f1);
            unpack2(acc[r][1], f2, f3);
            *reinterpret_cast<float4*>(gout + r * CAN_D) =
                make_float4(fmaxf(f0, 0.f), fmaxf(f1, 0.f),
                            fmaxf(f2, 0.f), fmaxf(f3, 0.f));
        }
    }
}

extern "C" void kernel_launch(void* const* d_in, const int* in_sizes, int n_in,
                              void* d_out, int out_size)
{
    const float* user = (const float*)d_in[0];
    const float* item = (const float*)d_in[1];
    float* out = (float*)d_out;

    const int B = in_sizes[0] / (CAN_N * CAN_D);   // 16384
    const int grid = (B + SPB - 1) / SPB;

    can_kernel<<<grid, TPB>>>(user, item, out, B);
}